// round 14
// baseline (speedup 1.0000x reference)
#include <cuda_runtime.h>
#include <cstdint>
#include <math.h>

#define BB 32
#define NN 22743
#define CC 80
#define KK 2048
#define CAP 4096
#define CAPC 512        // per-class box capacity in class_nms
#define RPB 96          // rows per block in score_kernel (96*85 % 4 == 0)
#define RPW 12          // rows per warp (8 warps * 12 = 96)

// ---------------- device scratch ----------------
__device__ float              g_mscore[BB * NN];
__device__ int                g_label[BB * NN];
__device__ unsigned long long g_keys[BB * CAP];
__device__ int                g_vcount[BB];
__device__ int                g_vc[BB];
__device__ int                g_topidx[BB * KK];
__device__ float              g_topscore[BB * KK];
__device__ float4             g_boxes[BB * KK];     // clipped, unscaled
__device__ int                g_labtop[BB * KK];
__device__ unsigned           g_maxbits[BB];        // max clipped coord (float bits)
__device__ unsigned char      g_keep[BB * KK];

// ---------------- init ----------------
__global__ void init_kernel() {
    int t = threadIdx.x;
    if (t < BB) { g_vcount[t] = 0; g_maxbits[t] = 0u; }
}

// ---------------- K1: score/label via smem-staged aligned streaming ----------------
__global__ void __launch_bounds__(256) score_kernel(const float* __restrict__ feat,
                                                    const float* __restrict__ pthresh) {
    __shared__ float sf[RPB * 85];          // 32640 B
    int tid  = threadIdx.x;
    int lane = tid & 31, wid = tid >> 5;
    int a0 = blockIdx.x * RPB;              // first global row of this block

    // aligned float4 streaming load (block start offset a0*85 is mult of 4)
    {
        const float4* src = (const float4*)(feat + (size_t)a0 * 85);
        float4* dst = (float4*)sf;
        #pragma unroll
        for (int i = 0; i < 8; i++) {
            int p = tid + i * 256;
            if (p < RPB * 85 / 4) dst[p] = src[p];
        }
    }
    __syncthreads();

    float thresh = *pthresh;
    #pragma unroll
    for (int la = 0; la < RPW; la++) {
        int local = wid * RPW + la;
        int a = a0 + local;                 // global row (exact tiling: 727776/96)
        const float* row = sf + local * 85;

        float rs = row[4];
        float v  = row[5 + lane];
        float v2 = row[5 + 32 + lane];
        float v3 = (lane < 16) ? row[5 + 64 + lane] : -1.0f;

        int bi = lane;
        if (v2 > v) { v = v2; bi = lane + 32; }
        if (lane < 16 && v3 > v) { v = v3; bi = lane + 64; }
        #pragma unroll
        for (int off = 16; off; off >>= 1) {
            float ov = __shfl_down_sync(0xffffffffu, v, off);
            int   oi = __shfl_down_sync(0xffffffffu, bi, off);
            if (ov > v || (ov == v && oi < bi)) { v = ov; bi = oi; }
        }
        if (lane == 0) {
            int b = a / NN;
            int i = a - b * NN;
            float sc = __fmul_rn(v, rs);
            float m  = (sc >= thresh) ? sc : -1.0f;
            g_mscore[a] = m;
            g_label[a]  = bi;
            if (sc >= thresh) {
                int pos = atomicAdd(&g_vcount[b], 1);
                if (pos < CAP) {
                    unsigned ord = __float_as_uint(m) ^ 0x80000000u;
                    g_keys[b * CAP + pos] =
                        ((unsigned long long)ord << 32) | (unsigned)(~(unsigned)i);
                }
            }
        }
    }
}

// ---------------- K2: sort valid keys (size next-pow2(V)) + fillers ----------------
__global__ void __launch_bounds__(1024) topk_kernel(const float* __restrict__ pthresh) {
    __shared__ unsigned long long sk[CAP];
    __shared__ int wsum[32];
    __shared__ int sbase;
    int b   = blockIdx.x;
    int tid = threadIdx.x;
    int lane = tid & 31, wid = tid >> 5;

    int V = g_vcount[b];
    if (V > CAP) V = CAP;
    int P = 1024;
    while (P < V) P <<= 1;

    for (int t = tid; t < P; t += 1024)
        sk[t] = (t < V) ? g_keys[b * CAP + t] : 0ull;
    __syncthreads();

    for (int k = 2; k <= P; k <<= 1) {
        for (int j = k >> 1; j > 0; j >>= 1) {
            for (int t = tid; t < P; t += 1024) {
                int l = t ^ j;
                if (l > t) {
                    bool desc = ((t & k) == 0);
                    unsigned long long a = sk[t], c = sk[l];
                    bool sw = desc ? (a < c) : (a > c);
                    if (sw) { sk[t] = c; sk[l] = a; }
                }
            }
            __syncthreads();
        }
    }

    int Vc = V < KK ? V : KK;
    if (tid == 0) { g_vc[b] = Vc; sbase = 0; }
    for (int t = tid; t < Vc; t += 1024) {
        unsigned long long key = sk[t];
        g_topidx[b * KK + t]   = (int)(~(unsigned)key);
        g_topscore[b * KK + t] = __uint_as_float(((unsigned)(key >> 32)) ^ 0x80000000u);
    }
    __syncthreads();

    int slots = KK - Vc;
    if (slots > 0) {
        float thresh = *pthresh;
        for (int t0 = 0; t0 < NN; t0 += 1024) {
            if (sbase >= slots) break;
            int anchor = t0 + tid;
            bool flag = (anchor < NN) && (g_mscore[b * NN + anchor] < thresh);
            unsigned blt = __ballot_sync(0xffffffffu, flag);
            if (lane == 0) wsum[wid] = __popc(blt);
            __syncthreads();
            int woff = 0;
            #pragma unroll
            for (int q = 0; q < 32; q++) woff += (q < wid) ? wsum[q] : 0;
            int pos = sbase + woff + __popc(blt & ((1u << lane) - 1u));
            if (flag && pos < slots) {
                g_topidx[b * KK + Vc + pos]   = anchor;
                g_topscore[b * KK + Vc + pos] = -1.0f;
            }
            __syncthreads();
            if (tid == 0) {
                int tot = 0;
                #pragma unroll
                for (int q = 0; q < 32; q++) tot += wsum[q];
                sbase += tot;
            }
            __syncthreads();
        }
    }
}

// ---------------- K3: decode + clip, 4 items/thread software-pipelined ----------------
__global__ void __launch_bounds__(256) decode_kernel(const float* __restrict__ feat,
                                                     const float* __restrict__ anchors,
                                                     const float* __restrict__ sizes) {
    int g = blockIdx.x * blockDim.x + threadIdx.x;   // group id, 4 items each
    if (g >= BB * KK / 4) return;
    int t0 = g * 4;
    int b  = t0 / KK;
    float H = sizes[b * 2 + 0];
    float W = sizes[b * 2 + 1];
    float Wm1 = __fsub_rn(W, 1.0f);
    float Hm1 = __fsub_rn(H, 1.0f);

    int4 iv = *(const int4*)&g_topidx[t0];
    int idxs[4] = {iv.x, iv.y, iv.z, iv.w};

    float r0[4], r1[4], r2[4], r3[4];
    float a0[4], a1[4], a2[4], a3[4], a4[4];
    int   lb[4];
    #pragma unroll
    for (int e = 0; e < 4; e++) {
        const float* r = feat + ((size_t)b * NN + idxs[e]) * 85;
        const float* a = anchors + (size_t)idxs[e] * 5;
        r0[e] = __ldg(r + 0); r1[e] = __ldg(r + 1);
        r2[e] = __ldg(r + 2); r3[e] = __ldg(r + 3);
        a0[e] = __ldg(a + 0); a1[e] = __ldg(a + 1); a2[e] = __ldg(a + 2);
        a3[e] = __ldg(a + 3); a4[e] = __ldg(a + 4);
        lb[e] = g_label[b * NN + idxs[e]];
    }

    float mloc = 0.0f;
    #pragma unroll
    for (int e = 0; e < 4; e++) {
        float cx = __fmul_rn(__fadd_rn(r0[e], a0[e]), a2[e]);
        float cy = __fmul_rn(__fadd_rn(r1[e], a1[e]), a2[e]);
        float w  = __fmul_rn(a3[e], expf(r2[e]));
        float h  = __fmul_rn(a4[e], expf(r3[e]));
        float l  = __fsub_rn(cx, __fmul_rn(w, 0.5f));
        float tp = __fsub_rn(cy, __fmul_rn(h, 0.5f));
        float x2 = __fadd_rn(l, w);
        float y2 = __fadd_rn(tp, h);

        float b0 = fminf(fmaxf(l, 0.0f), Wm1);
        float b1 = fminf(fmaxf(tp, 0.0f), Hm1);
        float b2 = fminf(fmaxf(x2, 0.0f), Wm1);
        float b3 = fminf(fmaxf(y2, 0.0f), Hm1);

        g_boxes[t0 + e] = make_float4(b0, b1, b2, b3);
        g_labtop[t0 + e] = lb[e];
        mloc = fmaxf(mloc, fmaxf(fmaxf(b0, b1), fmaxf(b2, b3)));
    }

    // warp-uniform b (512 groups/image, 512 % 32 == 0) -> one atomic per warp
    unsigned mb = __float_as_uint(mloc);
    #pragma unroll
    for (int off = 16; off; off >>= 1)
        mb = max(mb, __shfl_xor_sync(0xffffffffu, mb, off));
    if ((threadIdx.x & 31) == 0)
        atomicMax(&g_maxbits[b], mb);
}

// ---------------- K4: per-class greedy NMS (1 warp per image,class) ----------------
// Cross-class IoU is exactly 0 under the label offset, so reference NMS
// decomposes into independent per-class forward greedy passes.
__global__ void __launch_bounds__(32) class_nms(const float* __restrict__ pnms) {
    __shared__ float lx1[CAPC], ly1[CAPC], lx2[CAPC], ly2[CAPC], lar[CAPC];
    __shared__ short lk[CAPC];
    __shared__ unsigned char act[CAPC];

    int c = blockIdx.x, b = blockIdx.y;
    int lane = threadIdx.x;
    int Vc = g_vc[b];
    float nth  = *pnms;
    float offm = __fadd_rn(__uint_as_float(g_maxbits[b]), 1.0f);
    float off  = __fmul_rn((float)c, offm);

    // gather this class's boxes in global (score-sorted) index order,
    // batching 4 label chunks per iteration to shorten the latency chain
    int n = 0;
    for (int k0 = 0; k0 < Vc; k0 += 128) {
        int  lv[4];
        #pragma unroll
        for (int s = 0; s < 4; s++) {
            int k = k0 + s * 32 + lane;
            lv[s] = (k < Vc) ? __ldg(&g_labtop[b * KK + k]) : -1;
        }
        #pragma unroll
        for (int s = 0; s < 4; s++) {
            int k = k0 + s * 32 + lane;
            bool f = (lv[s] == c);
            unsigned bl = __ballot_sync(0xffffffffu, f);
            if (f) {
                int pos = n + __popc(bl & ((1u << lane) - 1u));
                if (pos < CAPC) {
                    float4 bx = g_boxes[b * KK + k];
                    float x1 = __fadd_rn(bx.x, off);
                    float y1 = __fadd_rn(bx.y, off);
                    float x2 = __fadd_rn(bx.z, off);
                    float y2 = __fadd_rn(bx.w, off);
                    lx1[pos] = x1; ly1[pos] = y1; lx2[pos] = x2; ly2[pos] = y2;
                    lar[pos] = __fmul_rn(__fsub_rn(x2, x1), __fsub_rn(y2, y1));
                    lk[pos]  = (short)k;
                    act[pos] = 1;
                }
            }
            n += __popc(bl);
        }
    }
    if (n > CAPC) n = CAPC;
    __syncwarp();

    // forward greedy within class
    for (int i = 0; i < n; i++) {
        if (act[i]) {
            float ix1 = lx1[i], iy1 = ly1[i], ix2 = lx2[i], iy2 = ly2[i], ia = lar[i];
            for (int j = i + 1 + lane; j < n; j += 32) {
                if (!act[j]) continue;
                float w = fmaxf(__fsub_rn(fminf(ix2, lx2[j]), fmaxf(ix1, lx1[j])), 0.0f);
                float h = fmaxf(__fsub_rn(fminf(iy2, ly2[j]), fmaxf(iy1, ly1[j])), 0.0f);
                float inter = __fmul_rn(w, h);
                float denom = __fadd_rn(__fsub_rn(__fadd_rn(ia, lar[j]), inter), 1e-9f);
                if (inter / denom > nth) act[j] = 0;
            }
        }
        __syncwarp();
    }

    for (int t = lane; t < n; t += 32)
        g_keep[b * KK + lk[t]] = act[t];
}

// ---------------- K5: outputs (one item/thread, wide grid) ----------------
__global__ void __launch_bounds__(256) out_kernel(const float* __restrict__ sizes,
                                                  const float* __restrict__ sizes_ori,
                                                  float* __restrict__ out) {
    int b = blockIdx.x;
    int k = blockIdx.y * 256 + threadIdx.x;          // grid.y = KK/256 = 8
    int Vc = g_vc[b];
    float scale = sizes_ori[b * 2] / sizes[b * 2];
    const size_t OS = (size_t)BB * KK * 4;
    const size_t OL = OS + (size_t)BB * KK;
    const size_t OK = OL + (size_t)BB * KK;

    size_t gk = (size_t)b * KK + k;
    float4 bx = g_boxes[gk];
    ((float4*)out)[gk] = make_float4(__fmul_rn(bx.x, scale), __fmul_rn(bx.y, scale),
                                     __fmul_rn(bx.z, scale), __fmul_rn(bx.w, scale));
    out[OS + gk] = g_topscore[gk];
    out[OL + gk] = (float)g_labtop[gk];
    out[OK + gk] = (k < Vc && g_keep[gk]) ? 1.0f : 0.0f;
}

// ---------------- launcher ----------------
extern "C" void kernel_launch(void* const* d_in, const int* in_sizes, int n_in,
                              void* d_out, int out_size) {
    const float* feat      = (const float*)d_in[0];
    const float* anchors   = (const float*)d_in[1];
    const float* sizes     = (const float*)d_in[2];
    const float* sizes_ori = (const float*)d_in[3];
    const float* pthresh   = (const float*)d_in[4];
    const float* pnms      = (const float*)d_in[5];
    float* out = (float*)d_out;

    init_kernel<<<1, BB>>>();
    score_kernel<<<BB * NN / RPB, 256>>>(feat, pthresh);   // 727776/96 = 7581 exact
    topk_kernel<<<BB, 1024>>>(pthresh);
    decode_kernel<<<(BB * KK / 4 + 255) / 256, 256>>>(feat, anchors, sizes);
    dim3 cg(CC, BB);
    class_nms<<<cg, 32>>>(pnms);
    dim3 og(BB, KK / 256);
    out_kernel<<<og, 256>>>(sizes, sizes_ori, out);
}

// round 15
// speedup vs baseline: 1.2302x; 1.2302x over previous
#include <cuda_runtime.h>
#include <cstdint>
#include <math.h>

#define BB 32
#define NN 22743
#define CC 80
#define KK 2048
#define CAP 4096
#define CAPC 512        // per-class box capacity in class_nms
#define RPB 96          // rows per block in score_kernel (96*85 % 4 == 0)
#define RPW 12          // rows per warp (8 warps * 12 = 96)

// ---------------- device scratch (zero-initialized at load; out_kernel re-zeros
// g_vcount/g_maxbits at the end of every invocation for the next one) ----------
__device__ float              g_mscore[BB * NN];
__device__ int                g_label[BB * NN];
__device__ unsigned long long g_keys[BB * CAP];
__device__ int                g_vcount[BB];
__device__ int                g_vc[BB];
__device__ int                g_topidx[BB * KK];
__device__ float              g_topscore[BB * KK];
__device__ float4             g_boxes[BB * KK];     // clipped, unscaled
__device__ int                g_labtop[BB * KK];
__device__ unsigned           g_maxbits[BB];        // max clipped coord (float bits)
__device__ unsigned char      g_keep[BB * KK];

// ---------------- K1: score/label via smem staging + redux argmax ----------------
__global__ void __launch_bounds__(256) score_kernel(const float* __restrict__ feat,
                                                    const float* __restrict__ pthresh) {
    __shared__ float sf[RPB * 85];          // 32640 B
    int tid  = threadIdx.x;
    int lane = tid & 31, wid = tid >> 5;
    int a0 = blockIdx.x * RPB;              // first global row of this block

    // aligned float4 streaming load (block start offset a0*85 is mult of 4)
    {
        const float4* src = (const float4*)(feat + (size_t)a0 * 85);
        float4* dst = (float4*)sf;
        #pragma unroll
        for (int i = 0; i < 8; i++) {
            int p = tid + i * 256;
            if (p < RPB * 85 / 4) dst[p] = src[p];
        }
    }
    __syncthreads();

    float thresh = *pthresh;
    #pragma unroll
    for (int la = 0; la < RPW; la++) {
        int local = wid * RPW + la;
        int a = a0 + local;                 // global row (exact tiling: 727776/96)
        const float* row = sf + local * 85;

        float rs = row[4];
        // positive floats: u32 bit order == float order
        unsigned c1 = __float_as_uint(row[5 + lane]);
        unsigned c2 = __float_as_uint(row[5 + 32 + lane]);
        unsigned c3 = (lane < 16) ? __float_as_uint(row[5 + 64 + lane]) : 0u;

        unsigned mx   = max(c1, max(c2, c3));
        unsigned vmax = __reduce_max_sync(0xffffffffu, mx);
        // smallest class index achieving the (bit-exact) max -> JAX argmax tie-break
        unsigned idx = 0xffffffffu;
        if (c3 == vmax) idx = lane + 64;
        if (c2 == vmax) idx = lane + 32;
        if (c1 == vmax) idx = lane;
        unsigned imin = __reduce_min_sync(0xffffffffu, idx);

        if (lane == 0) {
            int b = a / NN;
            int i = a - b * NN;
            float v  = __uint_as_float(vmax);
            float sc = __fmul_rn(v, rs);
            float m  = (sc >= thresh) ? sc : -1.0f;
            g_mscore[a] = m;
            g_label[a]  = (int)imin;
            if (sc >= thresh) {
                int pos = atomicAdd(&g_vcount[b], 1);
                if (pos < CAP) {
                    unsigned ord = __float_as_uint(m) ^ 0x80000000u;
                    g_keys[b * CAP + pos] =
                        ((unsigned long long)ord << 32) | (unsigned)(~(unsigned)i);
                }
            }
        }
    }
}

// ---------------- K2: sort valid keys (size next-pow2(V)) + fillers ----------------
__global__ void __launch_bounds__(1024) topk_kernel(const float* __restrict__ pthresh) {
    __shared__ unsigned long long sk[CAP];
    __shared__ int wsum[32];
    __shared__ int sbase;
    int b   = blockIdx.x;
    int tid = threadIdx.x;
    int lane = tid & 31, wid = tid >> 5;

    int V = g_vcount[b];
    if (V > CAP) V = CAP;
    int P = 1024;
    while (P < V) P <<= 1;

    for (int t = tid; t < P; t += 1024)
        sk[t] = (t < V) ? g_keys[b * CAP + t] : 0ull;
    __syncthreads();

    for (int k = 2; k <= P; k <<= 1) {
        for (int j = k >> 1; j > 0; j >>= 1) {
            for (int t = tid; t < P; t += 1024) {
                int l = t ^ j;
                if (l > t) {
                    bool desc = ((t & k) == 0);
                    unsigned long long a = sk[t], c = sk[l];
                    bool sw = desc ? (a < c) : (a > c);
                    if (sw) { sk[t] = c; sk[l] = a; }
                }
            }
            __syncthreads();
        }
    }

    int Vc = V < KK ? V : KK;
    if (tid == 0) { g_vc[b] = Vc; sbase = 0; }
    for (int t = tid; t < Vc; t += 1024) {
        unsigned long long key = sk[t];
        g_topidx[b * KK + t]   = (int)(~(unsigned)key);
        g_topscore[b * KK + t] = __uint_as_float(((unsigned)(key >> 32)) ^ 0x80000000u);
    }
    __syncthreads();

    int slots = KK - Vc;
    if (slots > 0) {
        float thresh = *pthresh;
        for (int t0 = 0; t0 < NN; t0 += 1024) {
            if (sbase >= slots) break;
            int anchor = t0 + tid;
            bool flag = (anchor < NN) && (g_mscore[b * NN + anchor] < thresh);
            unsigned blt = __ballot_sync(0xffffffffu, flag);
            if (lane == 0) wsum[wid] = __popc(blt);
            __syncthreads();
            int woff = 0;
            #pragma unroll
            for (int q = 0; q < 32; q++) woff += (q < wid) ? wsum[q] : 0;
            int pos = sbase + woff + __popc(blt & ((1u << lane) - 1u));
            if (flag && pos < slots) {
                g_topidx[b * KK + Vc + pos]   = anchor;
                g_topscore[b * KK + Vc + pos] = -1.0f;
            }
            __syncthreads();
            if (tid == 0) {
                int tot = 0;
                #pragma unroll
                for (int q = 0; q < 32; q++) tot += wsum[q];
                sbase += tot;
            }
            __syncthreads();
        }
    }
}

// ---------------- K3: decode + clip, 4 items/thread software-pipelined ----------------
__global__ void __launch_bounds__(256) decode_kernel(const float* __restrict__ feat,
                                                     const float* __restrict__ anchors,
                                                     const float* __restrict__ sizes) {
    int g = blockIdx.x * blockDim.x + threadIdx.x;   // group id, 4 items each
    if (g >= BB * KK / 4) return;
    int t0 = g * 4;
    int b  = t0 / KK;
    float H = sizes[b * 2 + 0];
    float W = sizes[b * 2 + 1];
    float Wm1 = __fsub_rn(W, 1.0f);
    float Hm1 = __fsub_rn(H, 1.0f);

    int4 iv = *(const int4*)&g_topidx[t0];
    int idxs[4] = {iv.x, iv.y, iv.z, iv.w};

    float r0[4], r1[4], r2[4], r3[4];
    float a0[4], a1[4], a2[4], a3[4], a4[4];
    int   lb[4];
    #pragma unroll
    for (int e = 0; e < 4; e++) {
        const float* r = feat + ((size_t)b * NN + idxs[e]) * 85;
        const float* a = anchors + (size_t)idxs[e] * 5;
        r0[e] = __ldg(r + 0); r1[e] = __ldg(r + 1);
        r2[e] = __ldg(r + 2); r3[e] = __ldg(r + 3);
        a0[e] = __ldg(a + 0); a1[e] = __ldg(a + 1); a2[e] = __ldg(a + 2);
        a3[e] = __ldg(a + 3); a4[e] = __ldg(a + 4);
        lb[e] = g_label[b * NN + idxs[e]];
    }

    float mloc = 0.0f;
    #pragma unroll
    for (int e = 0; e < 4; e++) {
        float cx = __fmul_rn(__fadd_rn(r0[e], a0[e]), a2[e]);
        float cy = __fmul_rn(__fadd_rn(r1[e], a1[e]), a2[e]);
        float w  = __fmul_rn(a3[e], expf(r2[e]));
        float h  = __fmul_rn(a4[e], expf(r3[e]));
        float l  = __fsub_rn(cx, __fmul_rn(w, 0.5f));
        float tp = __fsub_rn(cy, __fmul_rn(h, 0.5f));
        float x2 = __fadd_rn(l, w);
        float y2 = __fadd_rn(tp, h);

        float b0 = fminf(fmaxf(l, 0.0f), Wm1);
        float b1 = fminf(fmaxf(tp, 0.0f), Hm1);
        float b2 = fminf(fmaxf(x2, 0.0f), Wm1);
        float b3 = fminf(fmaxf(y2, 0.0f), Hm1);

        g_boxes[t0 + e] = make_float4(b0, b1, b2, b3);
        g_labtop[t0 + e] = lb[e];
        mloc = fmaxf(mloc, fmaxf(fmaxf(b0, b1), fmaxf(b2, b3)));
    }

    // warp-uniform b (512 groups/image, 512 % 32 == 0) -> one atomic per warp
    unsigned mb = __reduce_max_sync(0xffffffffu, __float_as_uint(mloc));
    if ((threadIdx.x & 31) == 0)
        atomicMax(&g_maxbits[b], mb);
}

// ---------------- K4: per-class greedy NMS (1 warp per image,class) ----------------
// Cross-class IoU is exactly 0 under the label offset, so reference NMS
// decomposes into independent per-class forward greedy passes.
__global__ void __launch_bounds__(32) class_nms(const float* __restrict__ pnms) {
    __shared__ float lx1[CAPC], ly1[CAPC], lx2[CAPC], ly2[CAPC], lar[CAPC];
    __shared__ short lk[CAPC];
    __shared__ unsigned char act[CAPC];

    int c = blockIdx.x, b = blockIdx.y;
    int lane = threadIdx.x;
    int Vc = g_vc[b];
    float nth  = *pnms;
    float offm = __fadd_rn(__uint_as_float(g_maxbits[b]), 1.0f);
    float off  = __fmul_rn((float)c, offm);

    // gather this class's boxes in global (score-sorted) index order,
    // batching 4 label chunks per iteration to shorten the latency chain
    int n = 0;
    for (int k0 = 0; k0 < Vc; k0 += 128) {
        int  lv[4];
        #pragma unroll
        for (int s = 0; s < 4; s++) {
            int k = k0 + s * 32 + lane;
            lv[s] = (k < Vc) ? __ldg(&g_labtop[b * KK + k]) : -1;
        }
        #pragma unroll
        for (int s = 0; s < 4; s++) {
            int k = k0 + s * 32 + lane;
            bool f = (lv[s] == c);
            unsigned bl = __ballot_sync(0xffffffffu, f);
            if (f) {
                int pos = n + __popc(bl & ((1u << lane) - 1u));
                if (pos < CAPC) {
                    float4 bx = g_boxes[b * KK + k];
                    float x1 = __fadd_rn(bx.x, off);
                    float y1 = __fadd_rn(bx.y, off);
                    float x2 = __fadd_rn(bx.z, off);
                    float y2 = __fadd_rn(bx.w, off);
                    lx1[pos] = x1; ly1[pos] = y1; lx2[pos] = x2; ly2[pos] = y2;
                    lar[pos] = __fmul_rn(__fsub_rn(x2, x1), __fsub_rn(y2, y1));
                    lk[pos]  = (short)k;
                    act[pos] = 1;
                }
            }
            n += __popc(bl);
        }
    }
    if (n > CAPC) n = CAPC;
    __syncwarp();

    // forward greedy within class
    for (int i = 0; i < n; i++) {
        if (act[i]) {
            float ix1 = lx1[i], iy1 = ly1[i], ix2 = lx2[i], iy2 = ly2[i], ia = lar[i];
            for (int j = i + 1 + lane; j < n; j += 32) {
                if (!act[j]) continue;
                float w = fmaxf(__fsub_rn(fminf(ix2, lx2[j]), fmaxf(ix1, lx1[j])), 0.0f);
                float h = fmaxf(__fsub_rn(fminf(iy2, ly2[j]), fmaxf(iy1, ly1[j])), 0.0f);
                float inter = __fmul_rn(w, h);
                float denom = __fadd_rn(__fsub_rn(__fadd_rn(ia, lar[j]), inter), 1e-9f);
                if (inter / denom > nth) act[j] = 0;
            }
        }
        __syncwarp();
    }

    for (int t = lane; t < n; t += 32)
        g_keep[b * KK + lk[t]] = act[t];
}

// ---------------- K5: outputs + state reset for the next invocation ----------------
__global__ void __launch_bounds__(256) out_kernel(const float* __restrict__ sizes,
                                                  const float* __restrict__ sizes_ori,
                                                  float* __restrict__ out) {
    int b = blockIdx.x;
    int k = blockIdx.y * 256 + threadIdx.x;          // grid.y = KK/256 = 8
    int Vc = g_vc[b];
    float scale = sizes_ori[b * 2] / sizes[b * 2];
    const size_t OS = (size_t)BB * KK * 4;
    const size_t OL = OS + (size_t)BB * KK;
    const size_t OK = OL + (size_t)BB * KK;

    size_t gk = (size_t)b * KK + k;
    float4 bx = g_boxes[gk];
    ((float4*)out)[gk] = make_float4(__fmul_rn(bx.x, scale), __fmul_rn(bx.y, scale),
                                     __fmul_rn(bx.z, scale), __fmul_rn(bx.w, scale));
    out[OS + gk] = g_topscore[gk];
    out[OL + gk] = (float)g_labtop[gk];
    out[OK + gk] = (k < Vc && g_keep[gk]) ? 1.0f : 0.0f;

    // reset per-invocation counters for the next kernel_launch execution
    // (globals start zeroed at module load, so the first run is also clean)
    if (b == 0 && blockIdx.y == 0 && threadIdx.x < BB) {
        g_vcount[threadIdx.x]  = 0;
        g_maxbits[threadIdx.x] = 0u;
    }
}

// ---------------- launcher ----------------
extern "C" void kernel_launch(void* const* d_in, const int* in_sizes, int n_in,
                              void* d_out, int out_size) {
    const float* feat      = (const float*)d_in[0];
    const float* anchors   = (const float*)d_in[1];
    const float* sizes     = (const float*)d_in[2];
    const float* sizes_ori = (const float*)d_in[3];
    const float* pthresh   = (const float*)d_in[4];
    const float* pnms      = (const float*)d_in[5];
    float* out = (float*)d_out;

    score_kernel<<<BB * NN / RPB, 256>>>(feat, pthresh);   // 727776/96 = 7581 exact
    topk_kernel<<<BB, 1024>>>(pthresh);
    decode_kernel<<<(BB * KK / 4 + 255) / 256, 256>>>(feat, anchors, sizes);
    dim3 cg(CC, BB);
    class_nms<<<cg, 32>>>(pnms);
    dim3 og(BB, KK / 256);
    out_kernel<<<og, 256>>>(sizes, sizes_ori, out);
}

// round 17
// speedup vs baseline: 1.3009x; 1.0575x over previous
#include <cuda_runtime.h>
#include <cstdint>
#include <math.h>

#define BB 32
#define NN 22743
#define CC 80
#define KK 2048
#define CAP 4096
#define CAPC 512        // per-class box capacity in class_nms
#define RPB 96          // rows per block in score_kernel (96*85 % 4 == 0)
#define RPW 12          // rows per warp (8 warps * 12 = 96)
#define CMW 64          // mask words per (image,class): 64*32 = 2048 bits

// ---------------- device scratch (zero-initialized at load; out_kernel re-zeros
// the per-invocation state at the end of every run for the next one) -----------
__device__ float              g_mscore[BB * NN];
__device__ int                g_label[BB * NN];
__device__ unsigned long long g_keys[BB * CAP];
__device__ int                g_vcount[BB];
__device__ int                g_vc[BB];
__device__ int                g_topidx[BB * KK];
__device__ float              g_topscore[BB * KK];
__device__ float4             g_boxes[BB * KK];     // clipped, unscaled
__device__ int                g_labtop[BB * KK];
__device__ unsigned           g_maxbits[BB];        // max clipped coord (float bits)
__device__ unsigned char      g_keep[BB * KK];
__device__ unsigned           g_cmask[BB * CC * CMW]; // per-(image,class) slot bitmask

// ---------------- K1: score/label via smem staging + redux argmax ----------------
__global__ void __launch_bounds__(256) score_kernel(const float* __restrict__ feat,
                                                    const float* __restrict__ pthresh) {
    __shared__ float sf[RPB * 85];          // 32640 B
    int tid  = threadIdx.x;
    int lane = tid & 31, wid = tid >> 5;
    int a0 = blockIdx.x * RPB;              // first global row of this block

    // aligned float4 streaming load (block start offset a0*85 is mult of 4)
    {
        const float4* src = (const float4*)(feat + (size_t)a0 * 85);
        float4* dst = (float4*)sf;
        #pragma unroll
        for (int i = 0; i < 8; i++) {
            int p = tid + i * 256;
            if (p < RPB * 85 / 4) dst[p] = src[p];
        }
    }
    __syncthreads();

    float thresh = *pthresh;
    #pragma unroll
    for (int la = 0; la < RPW; la++) {
        int local = wid * RPW + la;
        int a = a0 + local;                 // global row (exact tiling: 727776/96)
        const float* row = sf + local * 85;

        float rs = row[4];
        // positive floats: u32 bit order == float order
        unsigned c1 = __float_as_uint(row[5 + lane]);
        unsigned c2 = __float_as_uint(row[5 + 32 + lane]);
        unsigned c3 = (lane < 16) ? __float_as_uint(row[5 + 64 + lane]) : 0u;

        unsigned mx   = max(c1, max(c2, c3));
        unsigned vmax = __reduce_max_sync(0xffffffffu, mx);
        // smallest class index achieving the (bit-exact) max -> JAX argmax tie-break
        unsigned idx = 0xffffffffu;
        if (c3 == vmax) idx = lane + 64;
        if (c2 == vmax) idx = lane + 32;
        if (c1 == vmax) idx = lane;
        unsigned imin = __reduce_min_sync(0xffffffffu, idx);

        if (lane == 0) {
            int b = a / NN;
            int i = a - b * NN;
            float v  = __uint_as_float(vmax);
            float sc = __fmul_rn(v, rs);
            float m  = (sc >= thresh) ? sc : -1.0f;
            g_mscore[a] = m;
            g_label[a]  = (int)imin;
            if (sc >= thresh) {
                int pos = atomicAdd(&g_vcount[b], 1);
                if (pos < CAP) {
                    unsigned ord = __float_as_uint(m) ^ 0x80000000u;
                    g_keys[b * CAP + pos] =
                        ((unsigned long long)ord << 32) | (unsigned)(~(unsigned)i);
                }
            }
        }
    }
}

// ---------------- K2: sort valid keys (size next-pow2(V)) + fillers ----------------
__global__ void __launch_bounds__(1024) topk_kernel(const float* __restrict__ pthresh) {
    __shared__ unsigned long long sk[CAP];
    __shared__ int wsum[32];
    __shared__ int sbase;
    int b   = blockIdx.x;
    int tid = threadIdx.x;
    int lane = tid & 31, wid = tid >> 5;

    int V = g_vcount[b];
    if (V > CAP) V = CAP;
    int P = 1024;
    while (P < V) P <<= 1;

    for (int t = tid; t < P; t += 1024)
        sk[t] = (t < V) ? g_keys[b * CAP + t] : 0ull;
    __syncthreads();

    for (int k = 2; k <= P; k <<= 1) {
        for (int j = k >> 1; j > 0; j >>= 1) {
            for (int t = tid; t < P; t += 1024) {
                int l = t ^ j;
                if (l > t) {
                    bool desc = ((t & k) == 0);
                    unsigned long long a = sk[t], c = sk[l];
                    bool sw = desc ? (a < c) : (a > c);
                    if (sw) { sk[t] = c; sk[l] = a; }
                }
            }
            __syncthreads();
        }
    }

    int Vc = V < KK ? V : KK;
    if (tid == 0) { g_vc[b] = Vc; sbase = 0; }
    for (int t = tid; t < Vc; t += 1024) {
        unsigned long long key = sk[t];
        g_topidx[b * KK + t]   = (int)(~(unsigned)key);
        g_topscore[b * KK + t] = __uint_as_float(((unsigned)(key >> 32)) ^ 0x80000000u);
    }
    __syncthreads();

    int slots = KK - Vc;
    if (slots > 0) {
        float thresh = *pthresh;
        for (int t0 = 0; t0 < NN; t0 += 1024) {
            if (sbase >= slots) break;
            int anchor = t0 + tid;
            bool flag = (anchor < NN) && (g_mscore[b * NN + anchor] < thresh);
            unsigned blt = __ballot_sync(0xffffffffu, flag);
            if (lane == 0) wsum[wid] = __popc(blt);
            __syncthreads();
            int woff = 0;
            #pragma unroll
            for (int q = 0; q < 32; q++) woff += (q < wid) ? wsum[q] : 0;
            int pos = sbase + woff + __popc(blt & ((1u << lane) - 1u));
            if (flag && pos < slots) {
                g_topidx[b * KK + Vc + pos]   = anchor;
                g_topscore[b * KK + Vc + pos] = -1.0f;
            }
            __syncthreads();
            if (tid == 0) {
                int tot = 0;
                #pragma unroll
                for (int q = 0; q < 32; q++) tot += wsum[q];
                sbase += tot;
            }
            __syncthreads();
        }
    }
}

// ---------------- K3: decode + clip + class-mask build ----------------
__global__ void __launch_bounds__(256) decode_kernel(const float* __restrict__ feat,
                                                     const float* __restrict__ anchors,
                                                     const float* __restrict__ sizes) {
    int g = blockIdx.x * blockDim.x + threadIdx.x;   // group id, 4 items each
    if (g >= BB * KK / 4) return;
    int t0 = g * 4;
    int b  = t0 / KK;
    int Vc = g_vc[b];
    float H = sizes[b * 2 + 0];
    float W = sizes[b * 2 + 1];
    float Wm1 = __fsub_rn(W, 1.0f);
    float Hm1 = __fsub_rn(H, 1.0f);

    int4 iv = *(const int4*)&g_topidx[t0];
    int idxs[4] = {iv.x, iv.y, iv.z, iv.w};

    float r0[4], r1[4], r2[4], r3[4];
    float a0[4], a1[4], a2[4], a3[4], a4[4];
    int   lb[4];
    #pragma unroll
    for (int e = 0; e < 4; e++) {
        const float* r = feat + ((size_t)b * NN + idxs[e]) * 85;
        const float* a = anchors + (size_t)idxs[e] * 5;
        r0[e] = __ldg(r + 0); r1[e] = __ldg(r + 1);
        r2[e] = __ldg(r + 2); r3[e] = __ldg(r + 3);
        a0[e] = __ldg(a + 0); a1[e] = __ldg(a + 1); a2[e] = __ldg(a + 2);
        a3[e] = __ldg(a + 3); a4[e] = __ldg(a + 4);
        lb[e] = g_label[b * NN + idxs[e]];
    }

    float mloc = 0.0f;
    #pragma unroll
    for (int e = 0; e < 4; e++) {
        int k = t0 + e;
        float cx = __fmul_rn(__fadd_rn(r0[e], a0[e]), a2[e]);
        float cy = __fmul_rn(__fadd_rn(r1[e], a1[e]), a2[e]);
        float w  = __fmul_rn(a3[e], expf(r2[e]));
        float h  = __fmul_rn(a4[e], expf(r3[e]));
        float l  = __fsub_rn(cx, __fmul_rn(w, 0.5f));
        float tp = __fsub_rn(cy, __fmul_rn(h, 0.5f));
        float x2 = __fadd_rn(l, w);
        float y2 = __fadd_rn(tp, h);

        float b0 = fminf(fmaxf(l, 0.0f), Wm1);
        float b1 = fminf(fmaxf(tp, 0.0f), Hm1);
        float b2 = fminf(fmaxf(x2, 0.0f), Wm1);
        float b3 = fminf(fmaxf(y2, 0.0f), Hm1);

        g_boxes[k] = make_float4(b0, b1, b2, b3);
        g_labtop[k] = lb[e];
        mloc = fmaxf(mloc, fmaxf(fmaxf(b0, b1), fmaxf(b2, b3)));

        int kk = k - b * KK;                 // slot within image
        if (kk < Vc)                         // fillers never enter the mask
            atomicOr(&g_cmask[(b * CC + lb[e]) * CMW + (kk >> 5)], 1u << (kk & 31));
    }

    // warp-uniform b (512 groups/image, 512 % 32 == 0) -> one atomic per warp
    unsigned mb = __reduce_max_sync(0xffffffffu, __float_as_uint(mloc));
    if ((threadIdx.x & 31) == 0)
        atomicMax(&g_maxbits[b], mb);
}

// ---------------- K4: per-class greedy NMS via bitmask (1 warp/image,class) -------
__global__ void __launch_bounds__(32) class_nms(const float* __restrict__ pnms) {
    __shared__ float lx1[CAPC], ly1[CAPC], lx2[CAPC], ly2[CAPC], lar[CAPC];
    __shared__ short lk[CAPC];
    __shared__ unsigned char act[CAPC];

    int c = blockIdx.x, b = blockIdx.y;
    int lane = threadIdx.x;
    float nth  = *pnms;
    float offm = __fadd_rn(__uint_as_float(g_maxbits[b]), 1.0f);
    float off  = __fmul_rn((float)c, offm);

    // each lane owns 2 mask words = 64 slots: [lane*64, lane*64+64)
    const unsigned* cm = &g_cmask[(b * CC + c) * CMW];
    unsigned w0 = cm[lane * 2];
    unsigned w1 = cm[lane * 2 + 1];

    int cnt = __popc(w0) + __popc(w1);
    // inclusive warp prefix sum of cnt -> exclusive offset
    int pre = cnt;
    #pragma unroll
    for (int o = 1; o < 32; o <<= 1) {
        int t = __shfl_up_sync(0xffffffffu, pre, o);
        if (lane >= o) pre += t;
    }
    int excl = pre - cnt;
    int n = __shfl_sync(0xffffffffu, pre, 31);
    if (n > CAPC) n = CAPC;

    // gather member boxes in ascending-slot order (== score-descending)
    int pos = excl;
    unsigned t0 = w0;
    while (t0) {
        int bit = __ffs(t0) - 1; t0 &= t0 - 1;
        if (pos < CAPC) {
            int k = lane * 64 + bit;
            float4 bx = g_boxes[b * KK + k];
            float x1 = __fadd_rn(bx.x, off);
            float y1 = __fadd_rn(bx.y, off);
            float x2 = __fadd_rn(bx.z, off);
            float y2 = __fadd_rn(bx.w, off);
            lx1[pos] = x1; ly1[pos] = y1; lx2[pos] = x2; ly2[pos] = y2;
            lar[pos] = __fmul_rn(__fsub_rn(x2, x1), __fsub_rn(y2, y1));
            lk[pos]  = (short)k;
            act[pos] = 1;
        }
        pos++;
    }
    unsigned t1 = w1;
    while (t1) {
        int bit = __ffs(t1) - 1; t1 &= t1 - 1;
        if (pos < CAPC) {
            int k = lane * 64 + 32 + bit;
            float4 bx = g_boxes[b * KK + k];
            float x1 = __fadd_rn(bx.x, off);
            float y1 = __fadd_rn(bx.y, off);
            float x2 = __fadd_rn(bx.z, off);
            float y2 = __fadd_rn(bx.w, off);
            lx1[pos] = x1; ly1[pos] = y1; lx2[pos] = x2; ly2[pos] = y2;
            lar[pos] = __fmul_rn(__fsub_rn(x2, x1), __fsub_rn(y2, y1));
            lk[pos]  = (short)k;
            act[pos] = 1;
        }
        pos++;
    }
    __syncwarp();

    // forward greedy within class
    for (int i = 0; i < n; i++) {
        if (act[i]) {
            float ix1 = lx1[i], iy1 = ly1[i], ix2 = lx2[i], iy2 = ly2[i], ia = lar[i];
            for (int j = i + 1 + lane; j < n; j += 32) {
                if (!act[j]) continue;
                float w = fmaxf(__fsub_rn(fminf(ix2, lx2[j]), fmaxf(ix1, lx1[j])), 0.0f);
                float h = fmaxf(__fsub_rn(fminf(iy2, ly2[j]), fmaxf(iy1, ly1[j])), 0.0f);
                float inter = __fmul_rn(w, h);
                float denom = __fadd_rn(__fsub_rn(__fadd_rn(ia, lar[j]), inter), 1e-9f);
                if (inter / denom > nth) act[j] = 0;
            }
        }
        __syncwarp();
    }

    for (int t = lane; t < n; t += 32)
        g_keep[b * KK + lk[t]] = act[t];
}

// ---------------- K5: outputs + state reset for the next invocation ----------------
__global__ void __launch_bounds__(256) out_kernel(const float* __restrict__ sizes,
                                                  const float* __restrict__ sizes_ori,
                                                  float* __restrict__ out) {
    int b = blockIdx.x;
    int k = blockIdx.y * 256 + threadIdx.x;          // grid.y = KK/256 = 8
    int Vc = g_vc[b];
    float scale = sizes_ori[b * 2] / sizes[b * 2];
    const size_t OS = (size_t)BB * KK * 4;
    const size_t OL = OS + (size_t)BB * KK;
    const size_t OK = OL + (size_t)BB * KK;

    size_t gk = (size_t)b * KK + k;
    float4 bx = g_boxes[gk];
    ((float4*)out)[gk] = make_float4(__fmul_rn(bx.x, scale), __fmul_rn(bx.y, scale),
                                     __fmul_rn(bx.z, scale), __fmul_rn(bx.w, scale));
    out[OS + gk] = g_topscore[gk];
    out[OL + gk] = (float)g_labtop[gk];
    out[OK + gk] = (k < Vc && g_keep[gk]) ? 1.0f : 0.0f;

    // reset per-invocation state for the next kernel_launch execution
    // (globals start zeroed at module load, so the first run is also clean)
    unsigned gt = (b * gridDim.y + blockIdx.y) * 256 + threadIdx.x;   // 0..65535
    for (unsigned i = gt; i < BB * CC * CMW; i += BB * (KK / 256) * 256)
        g_cmask[i] = 0u;
    if (gt < BB) {
        g_vcount[gt]  = 0;
        g_maxbits[gt] = 0u;
    }
}

// ---------------- launcher ----------------
extern "C" void kernel_launch(void* const* d_in, const int* in_sizes, int n_in,
                              void* d_out, int out_size) {
    const float* feat      = (const float*)d_in[0];
    const float* anchors   = (const float*)d_in[1];
    const float* sizes     = (const float*)d_in[2];
    const float* sizes_ori = (const float*)d_in[3];
    const float* pthresh   = (const float*)d_in[4];
    const float* pnms      = (const float*)d_in[5];
    float* out = (float*)d_out;

    score_kernel<<<BB * NN / RPB, 256>>>(feat, pthresh);   // 727776/96 = 7581 exact
    topk_kernel<<<BB, 1024>>>(pthresh);
    decode_kernel<<<(BB * KK / 4 + 255) / 256, 256>>>(feat, anchors, sizes);
    dim3 cg(CC, BB);
    class_nms<<<cg, 32>>>(pnms);
    dim3 og(BB, KK / 256);
    out_kernel<<<og, 256>>>(sizes, sizes_ori, out);
}